// round 1
// baseline (speedup 1.0000x reference)
#include <cuda_runtime.h>

// sLSTM persistent scan kernel for GB300 (sm_103a).
//
// Shapes: x(256,2048,64) f32, W(512,64), R(128,512), b(512) -> out(256,2048,128) f32.
//
// Design: 128 CTAs x 512 threads, each CTA owns 2 batch rows and runs the full
// 2048-step scan with NO inter-CTA communication. The folded weight matrix
// CW[k][g] (k<128: R[k][g]; k>=128: W[g][k-128]) is 192x512 fp32 = 384KB and is
// split: k in [0,84) held in per-thread registers (thread g owns column g),
// k in [84,192) held in shared memory. Per step each thread computes the full
// dot product for its gate column over both rows (h broadcast from smem, the
// smem-weight load amortized across both rows), then 256 threads do the
// exponential-gating state update (c,n,m live in their registers).

#define BB 256
#define SS 2048
#define II 64
#define HH 128
#define GG 512           // 4*H
#define KK 192           // H + I
#define REG_K 84
#define SMK 108          // KK - REG_K
#define NCTA 128
#define ROWS 2
#define NTHR 512

// smem: sW[SMK][GG] | hx[ROWS][KK] | gates[ROWS][GG]
#define SMEM_FLOATS (SMK * GG + ROWS * KK + ROWS * GG)
#define SMEM_BYTES  (SMEM_FLOATS * 4)

__global__ void __launch_bounds__(NTHR, 1)
slstm_kernel(const float* __restrict__ xg, const float* __restrict__ Wm,
             const float* __restrict__ Rm, const float* __restrict__ bias,
             float* __restrict__ out)
{
    extern __shared__ float smem[];
    float* sW    = smem;                       // [SMK][GG]
    float* hx    = smem + SMK * GG;            // [ROWS][KK]  (h | x_t per row)
    float* gates = hx + ROWS * KK;             // [ROWS][GG]

    const int tid = threadIdx.x;
    const int g   = tid;                       // owned gate column
    const int b0  = blockIdx.x * ROWS;

    // ---- load register-resident weights: CW[k][g], k in [0,REG_K) (all < H -> R) ----
    float w[REG_K];
#pragma unroll
    for (int k = 0; k < REG_K; k++)
        w[k] = Rm[k * GG + g];

    // ---- load smem-resident weights: k in [REG_K, KK) ----
    for (int idx = tid; idx < SMK * GG; idx += NTHR) {
        int kk = idx / GG + REG_K;
        int gg = idx % GG;
        float v = (kk < HH) ? Rm[kk * GG + gg] : Wm[gg * II + (kk - HH)];
        sW[idx] = v;
    }

    const float bg = bias[g];

    // ---- init hx: h(t=0)=0, x_0 loaded ----
    if (tid < ROWS * KK) {
        int row = tid / KK, kk = tid % KK;
        float v = 0.0f;
        if (kk >= HH)
            v = xg[((long long)(b0 + row)) * (SS * II) + (kk - HH)];
        hx[row * KK + kk] = v;
    }
    __syncthreads();

    // epilogue thread mapping (tid < 256): state owner for (row, hid)
    const int erow = tid >> 7;
    const int ehid = tid & 127;
    // x-prefetch mapping (256 <= tid < 384)
    const int prow = (tid - 256) >> 6;
    const int pxi  = (tid - 256) & 63;

    float c_ = 0.0f, n_ = 0.0f, m_ = 0.0f;
    float xpref = 0.0f;

    const float* hx0 = hx;
    const float* hx1 = hx + KK;
    const float* wp  = sW + g;

#pragma unroll 1
    for (int step = 0; step < SS; step++) {
        // prefetch x(step+1) into registers (latency hidden under mainloop)
        if (tid >= 256 && tid < 384 && step + 1 < SS) {
            xpref = __ldg(&xg[((long long)(b0 + prow)) * (SS * II)
                              + (long long)(step + 1) * II + pxi]);
        }

        // ---- mainloop: gates[row][g] = b[g] + sum_k hx[row][k] * CW[k][g] ----
        float a00 = bg, a01 = 0.0f;   // row 0, two chains
        float a10 = bg, a11 = 0.0f;   // row 1

#pragma unroll
        for (int k = 0; k < REG_K; k += 4) {
            float4 h0 = *(const float4*)(hx0 + k);
            float4 h1 = *(const float4*)(hx1 + k);
            a00 = fmaf(h0.x, w[k],     a00);
            a01 = fmaf(h0.y, w[k + 1], a01);
            a00 = fmaf(h0.z, w[k + 2], a00);
            a01 = fmaf(h0.w, w[k + 3], a01);
            a10 = fmaf(h1.x, w[k],     a10);
            a11 = fmaf(h1.y, w[k + 1], a11);
            a10 = fmaf(h1.z, w[k + 2], a10);
            a11 = fmaf(h1.w, w[k + 3], a11);
        }
#pragma unroll
        for (int k = 0; k < SMK; k += 4) {
            float4 h0 = *(const float4*)(hx0 + REG_K + k);
            float4 h1 = *(const float4*)(hx1 + REG_K + k);
            float w0 = wp[(k + 0) * GG];
            float w1 = wp[(k + 1) * GG];
            float w2 = wp[(k + 2) * GG];
            float w3 = wp[(k + 3) * GG];
            a00 = fmaf(h0.x, w0, a00);
            a01 = fmaf(h0.y, w1, a01);
            a00 = fmaf(h0.z, w2, a00);
            a01 = fmaf(h0.w, w3, a01);
            a10 = fmaf(h1.x, w0, a10);
            a11 = fmaf(h1.y, w1, a11);
            a10 = fmaf(h1.z, w2, a10);
            a11 = fmaf(h1.w, w3, a11);
        }

        gates[0 * GG + g] = a00 + a01;
        gates[1 * GG + g] = a10 + a11;
        __syncthreads();   // gates visible; all reads of hx(t) done

        if (tid < 256) {
            const float* gr = gates + erow * GG;
            float iv = gr[ehid];
            float fv = gr[HH + ehid];
            float ov = gr[2 * HH + ehid];
            float zv = gr[3 * HH + ehid];

            // stable log-sigmoid, exponential gating (matches JAX reference)
            float lf = fminf(fv, 0.0f) - log1pf(__expf(-fabsf(fv)));
            float mn = fmaxf(lf + m_, iv);
            float ip = __expf(iv - mn);
            float fp = __expf(lf + m_ - mn);
            c_ = fp * c_ + ip * tanhf(zv);
            n_ = fp * n_ + ip;
            m_ = mn;
            float sig_o = 1.0f / (1.0f + __expf(-ov));
            float hv = sig_o * tanhf(__fdividef(c_, n_));

            hx[erow * KK + ehid] = hv;                                   // h(t+1)
            out[((long long)(b0 + erow) * SS + step) * HH + ehid] = hv;  // output
        } else if (tid < 384 && step + 1 < SS) {
            hx[prow * KK + HH + pxi] = xpref;                            // x(t+1)
        }
        __syncthreads();   // hx(t+1) ready for next mainloop
    }
}

extern "C" void kernel_launch(void* const* d_in, const int* in_sizes, int n_in,
                              void* d_out, int out_size)
{
    const float* xg = (const float*)d_in[0];
    const float* Wm = (const float*)d_in[1];
    const float* Rm = (const float*)d_in[2];
    const float* bv = (const float*)d_in[3];
    // defensive: W has 512*64=32768 elems, R has 128*512=65536 — swap if order differs
    if (n_in >= 3 && in_sizes[1] == HH * GG && in_sizes[2] == GG * II) {
        const float* t = Wm; Wm = Rm; Rm = t;
    }
    float* out = (float*)d_out;

    cudaFuncSetAttribute(slstm_kernel,
                         cudaFuncAttributeMaxDynamicSharedMemorySize, SMEM_BYTES);
    slstm_kernel<<<NCTA, NTHR, SMEM_BYTES>>>(xg, Wm, Rm, bv, out);
}

// round 2
// speedup vs baseline: 1.0337x; 1.0337x over previous
#include <cuda_runtime.h>

// sLSTM persistent scan, round 2: f32x2 packed FMA (FFMA2) + vectorized smem weights.
//
// x(256,2048,64) f32, W(512,64), R(128,512), b(512) -> out(256,2048,128) f32.
// 128 CTAs x 512 threads, 2 batch rows per CTA, no inter-CTA comm.
// Folded CW[k][g] (k<128 -> R[k][g], else W[g][k-128]), k packed in PAIRS into
// 64-bit lanes so fma.rn.f32x2 does 2 FMAs/instr with no operand duplication:
//   regs: 42 pairs (k in [0,84))  -- 84 regs, same cost as scalar
//   smem: sW[g][k] for k in [84,192), read as LDS.128 (stride 27 float4, odd
//         -> conflict-free phases), reinterpreted as 2 x f32x2.

#define SS 2048
#define II 64
#define HH 128
#define GG 512
#define KK 192
#define REG_K 84            // must be multiple of 4
#define SMK 108             // KK - REG_K; SMK/4 must be ODD (bank-conflict-free)
#define NCTA 128
#define ROWS 2
#define NTHR 512

#define SMEM_FLOATS (SMK * GG + ROWS * KK + ROWS * GG)
#define SMEM_BYTES  (SMEM_FLOATS * 4)

typedef unsigned long long u64;

__device__ __forceinline__ u64 ffma2(u64 a, u64 b, u64 c) {
    u64 d;
    asm("fma.rn.f32x2 %0, %1, %2, %3;" : "=l"(d) : "l"(a), "l"(b), "l"(c));
    return d;
}
__device__ __forceinline__ u64 packf2(float lo, float hi) {
    u64 r;
    asm("mov.b64 %0, {%1, %2};" : "=l"(r) : "f"(lo), "f"(hi));
    return r;
}
__device__ __forceinline__ float2 unpackf2(u64 v) {
    float2 r;
    asm("mov.b64 {%0, %1}, %2;" : "=f"(r.x), "=f"(r.y) : "l"(v));
    return r;
}
__device__ __forceinline__ float fast_tanh(float x) {
    float xc = fminf(fmaxf(x, -12.0f), 12.0f);
    float e  = __expf(2.0f * xc);
    return __fdividef(e - 1.0f, e + 1.0f);
}

__global__ void __launch_bounds__(NTHR, 1)
slstm_kernel(const float* __restrict__ xg, const float* __restrict__ Wm,
             const float* __restrict__ Rm, const float* __restrict__ bias,
             float* __restrict__ out)
{
    extern __shared__ float smem[];
    float* sW    = smem;                       // [GG][SMK]  (column-major per thread)
    float* hx    = smem + SMK * GG;            // [ROWS][KK] (h | x_t)
    float* gates = hx + ROWS * KK;             // [ROWS][GG]

    const int tid = threadIdx.x;
    const int g   = tid;
    const int b0  = blockIdx.x * ROWS;

    // register weights: 42 packed pairs, k in [0,84) (all from R)
    u64 wreg[REG_K / 2];
#pragma unroll
    for (int j = 0; j < REG_K / 2; j++)
        wreg[j] = packf2(Rm[(2 * j) * GG + g], Rm[(2 * j + 1) * GG + g]);

    // smem weights, transposed: sW[g2*SMK + (k-REG_K)]
    for (int idx = tid; idx < SMK * GG; idx += NTHR) {
        int g2 = idx / SMK;
        int kk = idx % SMK + REG_K;
        sW[idx] = (kk < HH) ? Rm[kk * GG + g2] : Wm[g2 * II + (kk - HH)];
    }

    const float bg = bias[g];

    if (tid < ROWS * KK) {
        int row = tid / KK, kk = tid % KK;
        float v = 0.0f;
        if (kk >= HH)
            v = xg[((long long)(b0 + row)) * (SS * II) + (kk - HH)];
        hx[row * KK + kk] = v;
    }
    __syncthreads();

    const int erow = tid >> 7;                 // epilogue mapping (tid < 256)
    const int ehid = tid & 127;
    const int prow = (tid - 256) >> 6;         // x-prefetch mapping (256..383)
    const int pxi  = (tid - 256) & 63;

    float c_ = 0.0f, n_ = 0.0f, m_ = 0.0f;
    float xpref = 0.0f;

    const float* hx0 = hx;
    const float* hx1 = hx + KK;
    const float* sWg = sW + g * SMK;

#pragma unroll 1
    for (int step = 0; step < SS; step++) {
        if (tid >= 256 && tid < 384 && step + 1 < SS) {
            xpref = __ldg(&xg[((long long)(b0 + prow)) * (SS * II)
                              + (long long)(step + 1) * II + pxi]);
        }

        u64 aA0 = 0, aB0 = 0, aA1 = 0, aB1 = 0;

#pragma unroll
        for (int k = 0; k < REG_K; k += 4) {
            ulonglong2 h0 = *(const ulonglong2*)(hx0 + k);
            ulonglong2 h1 = *(const ulonglong2*)(hx1 + k);
            u64 wA = wreg[k / 2], wB = wreg[k / 2 + 1];
            aA0 = ffma2(h0.x, wA, aA0);
            aB0 = ffma2(h0.y, wB, aB0);
            aA1 = ffma2(h1.x, wA, aA1);
            aB1 = ffma2(h1.y, wB, aB1);
        }
#pragma unroll
        for (int k = 0; k < SMK; k += 4) {
            ulonglong2 wv = *(const ulonglong2*)(sWg + k);
            ulonglong2 h0 = *(const ulonglong2*)(hx0 + REG_K + k);
            ulonglong2 h1 = *(const ulonglong2*)(hx1 + REG_K + k);
            aA0 = ffma2(h0.x, wv.x, aA0);
            aB0 = ffma2(h0.y, wv.y, aB0);
            aA1 = ffma2(h1.x, wv.x, aA1);
            aB1 = ffma2(h1.y, wv.y, aB1);
        }

        float2 A0 = unpackf2(aA0), B0 = unpackf2(aB0);
        float2 A1 = unpackf2(aA1), B1 = unpackf2(aB1);
        gates[0 * GG + g] = (A0.x + A0.y) + (B0.x + B0.y) + bg;
        gates[1 * GG + g] = (A1.x + A1.y) + (B1.x + B1.y) + bg;
        __syncthreads();

        if (tid < 256) {
            const float* gr = gates + erow * GG;
            float iv = gr[ehid];
            float fv = gr[HH + ehid];
            float ov = gr[2 * HH + ehid];
            float zv = gr[3 * HH + ehid];

            // stable log-sigmoid + exponential gating (fast-math variants;
            // abs err ~1e-6, far under the 1e-3 gate)
            float lf = fminf(fv, 0.0f) - __logf(1.0f + __expf(-fabsf(fv)));
            float mn = fmaxf(lf + m_, iv);
            float ip = __expf(iv - mn);
            float fp = __expf(lf + m_ - mn);
            c_ = fp * c_ + ip * fast_tanh(zv);
            n_ = fp * n_ + ip;
            m_ = mn;
            float so = __fdividef(1.0f, 1.0f + __expf(-ov));
            float hv = so * fast_tanh(__fdividef(c_, n_));

            hx[erow * KK + ehid] = hv;
            out[((long long)(b0 + erow) * SS + step) * HH + ehid] = hv;
        } else if (tid < 384 && step + 1 < SS) {
            hx[prow * KK + HH + pxi] = xpref;
        }
        __syncthreads();
    }
}

extern "C" void kernel_launch(void* const* d_in, const int* in_sizes, int n_in,
                              void* d_out, int out_size)
{
    const float* xg = (const float*)d_in[0];
    const float* Wm = (const float*)d_in[1];
    const float* Rm = (const float*)d_in[2];
    const float* bv = (const float*)d_in[3];
    if (n_in >= 3 && in_sizes[1] == HH * GG && in_sizes[2] == GG * II) {
        const float* t = Wm; Wm = Rm; Rm = t;
    }
    float* out = (float*)d_out;

    cudaFuncSetAttribute(slstm_kernel,
                         cudaFuncAttributeMaxDynamicSharedMemorySize, SMEM_BYTES);
    slstm_kernel<<<NCTA, NTHR, SMEM_BYTES>>>(xg, Wm, Rm, bv, out);
}

// round 3
// speedup vs baseline: 1.4570x; 1.4095x over previous
#include <cuda_runtime.h>

// sLSTM persistent scan, round 3: smem-wavefront-optimized layout.
// 128 CTAs x 256 threads; each thread owns TWO gate columns (t, t+256) and both
// batch rows, so every smem byte (weights and h/x broadcast) feeds 4x FFMA2 work.
//  - 96 of 192 k-rows live in registers (192 regs/thread, full RF utilization)
//  - 96 k-rows stream from smem: 196KB/step = 1536 conflict-free phases
//  - h/x broadcast: 8 warps x 96 LDS.128 = 768 phases (halved vs 16 warps)

#define SS 2048
#define II 64
#define HH 128
#define GG 512
#define KK 192
#define REG_K 96            // k-rows in registers (mult of 4)
#define SMK   96            // k-rows in smem (KK - REG_K)
#define PTS  (SMK * 2 + 4)  // per-thread smem weight stride in floats (196: 28 mod 32 banks -> conflict-free)
#define NCTA 128
#define ROWS 2
#define NTHR 256

#define SW_FLOATS (NTHR * PTS)
#define SMEM_FLOATS (SW_FLOATS + ROWS * KK + ROWS * GG)
#define SMEM_BYTES  (SMEM_FLOATS * 4)

typedef unsigned long long u64;

__device__ __forceinline__ u64 ffma2(u64 a, u64 b, u64 c) {
    u64 d;
    asm("fma.rn.f32x2 %0, %1, %2, %3;" : "=l"(d) : "l"(a), "l"(b), "l"(c));
    return d;
}
__device__ __forceinline__ u64 packf2(float lo, float hi) {
    u64 r;
    asm("mov.b64 %0, {%1, %2};" : "=l"(r) : "f"(lo), "f"(hi));
    return r;
}
__device__ __forceinline__ float2 unpackf2(u64 v) {
    float2 r;
    asm("mov.b64 {%0, %1}, %2;" : "=f"(r.x), "=f"(r.y) : "l"(v));
    return r;
}
__device__ __forceinline__ float fast_tanh(float x) {
    float xc = fminf(fmaxf(x, -12.0f), 12.0f);
    float e  = __expf(2.0f * xc);
    return __fdividef(e - 1.0f, e + 1.0f);
}
// folded weight CW[k][g]: k<H -> R[k][g]; else W[g][k-H]
__device__ __forceinline__ float cw(const float* __restrict__ Rm,
                                    const float* __restrict__ Wm, int k, int g) {
    return (k < HH) ? Rm[k * GG + g] : Wm[g * II + (k - HH)];
}

__global__ void __launch_bounds__(NTHR, 1)
slstm_kernel(const float* __restrict__ xg, const float* __restrict__ Wm,
             const float* __restrict__ Rm, const float* __restrict__ bias,
             float* __restrict__ out)
{
    extern __shared__ float smem[];
    float* sW    = smem;                        // [NTHR][PTS] per-thread weight slab
    float* hx    = smem + SW_FLOATS;            // [ROWS][KK]
    float* gates = hx + ROWS * KK;              // [ROWS][GG]

    const int tid = threadIdx.x;
    const int c0  = tid;            // first owned gate column
    const int c1  = tid + NTHR;     // second owned gate column
    const int b0  = blockIdx.x * ROWS;

    // ---- register weights: k in [0, REG_K) (all from R), packed pairs per column ----
    u64 wr0[REG_K / 2], wr1[REG_K / 2];
#pragma unroll
    for (int j = 0; j < REG_K / 2; j++) {
        wr0[j] = packf2(Rm[(2 * j) * GG + c0], Rm[(2 * j + 1) * GG + c0]);
        wr1[j] = packf2(Rm[(2 * j) * GG + c1], Rm[(2 * j + 1) * GG + c1]);
    }

    // ---- smem weights: k in [REG_K, KK), interleaved per 4-k chunk:
    //      [c0(k0,k1), c1(k0,k1), c0(k2,k3), c1(k2,k3)] ----
    {
        float* slab = sW + tid * PTS;
        for (int kc = 0; kc < SMK; kc += 4) {
            int k = REG_K + kc;
            slab[kc * 2 + 0] = cw(Rm, Wm, k + 0, c0);
            slab[kc * 2 + 1] = cw(Rm, Wm, k + 1, c0);
            slab[kc * 2 + 2] = cw(Rm, Wm, k + 0, c1);
            slab[kc * 2 + 3] = cw(Rm, Wm, k + 1, c1);
            slab[kc * 2 + 4] = cw(Rm, Wm, k + 2, c0);
            slab[kc * 2 + 5] = cw(Rm, Wm, k + 3, c0);
            slab[kc * 2 + 6] = cw(Rm, Wm, k + 2, c1);
            slab[kc * 2 + 7] = cw(Rm, Wm, k + 3, c1);
        }
    }

    const float bg0 = bias[c0];
    const float bg1 = bias[c1];

    // ---- init hx ----
    for (int idx = tid; idx < ROWS * KK; idx += NTHR) {
        int row = idx / KK, kk = idx % KK;
        float v = 0.0f;
        if (kk >= HH)
            v = xg[((long long)(b0 + row)) * (SS * II) + (kk - HH)];
        hx[row * KK + kk] = v;
    }
    __syncthreads();

    const int erow = tid >> 7;     // epilogue: 256 threads = 2 rows x 128 hid
    const int ehid = tid & 127;
    const int prow = tid >> 6;     // x-prefetch: tid < 128 -> (row, xi)
    const int pxi  = tid & 63;

    float c_ = 0.0f, n_ = 0.0f, m_ = 0.0f;
    float xpref = 0.0f;

    const float* hx0 = hx;
    const float* hx1 = hx + KK;
    const float* sWg = sW + tid * PTS;

#pragma unroll 1
    for (int step = 0; step < SS; step++) {
        if (tid < 128 && step + 1 < SS) {
            xpref = __ldg(&xg[((long long)(b0 + prow)) * (SS * II)
                              + (long long)(step + 1) * II + pxi]);
        }

        // accumulators: a{col}{row}, packed f32x2 (lane sum at the end)
        u64 a00 = 0, a10 = 0, a01 = 0, a11 = 0;

#pragma unroll
        for (int k = 0; k < REG_K; k += 4) {
            ulonglong2 h0 = *(const ulonglong2*)(hx0 + k);
            ulonglong2 h1 = *(const ulonglong2*)(hx1 + k);
            int j = k / 2;
            a00 = ffma2(h0.x, wr0[j],     a00);
            a10 = ffma2(h0.x, wr1[j],     a10);
            a01 = ffma2(h1.x, wr0[j],     a01);
            a11 = ffma2(h1.x, wr1[j],     a11);
            a00 = ffma2(h0.y, wr0[j + 1], a00);
            a10 = ffma2(h0.y, wr1[j + 1], a10);
            a01 = ffma2(h1.y, wr0[j + 1], a01);
            a11 = ffma2(h1.y, wr1[j + 1], a11);
        }
#pragma unroll
        for (int k = 0; k < SMK; k += 4) {
            ulonglong2 wv0 = *(const ulonglong2*)(sWg + k * 2);      // c0(k,k+1), c1(k,k+1)
            ulonglong2 wv1 = *(const ulonglong2*)(sWg + k * 2 + 4);  // c0(k+2,k+3), c1(k+2,k+3)
            ulonglong2 h0  = *(const ulonglong2*)(hx0 + REG_K + k);
            ulonglong2 h1  = *(const ulonglong2*)(hx1 + REG_K + k);
            a00 = ffma2(h0.x, wv0.x, a00);
            a10 = ffma2(h0.x, wv0.y, a10);
            a01 = ffma2(h1.x, wv0.x, a01);
            a11 = ffma2(h1.x, wv0.y, a11);
            a00 = ffma2(h0.y, wv1.x, a00);
            a10 = ffma2(h0.y, wv1.y, a10);
            a01 = ffma2(h1.y, wv1.x, a01);
            a11 = ffma2(h1.y, wv1.y, a11);
        }

        float2 f00 = unpackf2(a00), f10 = unpackf2(a10);
        float2 f01 = unpackf2(a01), f11 = unpackf2(a11);
        gates[0 * GG + c0] = f00.x + f00.y + bg0;
        gates[0 * GG + c1] = f10.x + f10.y + bg1;
        gates[1 * GG + c0] = f01.x + f01.y + bg0;
        gates[1 * GG + c1] = f11.x + f11.y + bg1;
        __syncthreads();

        // ---- state update: all 256 threads own one (row, hid) ----
        {
            const float* gr = gates + erow * GG;
            float iv = gr[ehid];
            float fv = gr[HH + ehid];
            float ov = gr[2 * HH + ehid];
            float zv = gr[3 * HH + ehid];

            float lf = fminf(fv, 0.0f) - __logf(1.0f + __expf(-fabsf(fv)));
            float mn = fmaxf(lf + m_, iv);
            float ip = __expf(iv - mn);
            float fp = __expf(lf + m_ - mn);
            c_ = fp * c_ + ip * fast_tanh(zv);
            n_ = fp * n_ + ip;
            m_ = mn;
            float so = __fdividef(1.0f, 1.0f + __expf(-ov));
            float hv = so * fast_tanh(__fdividef(c_, n_));

            hx[erow * KK + ehid] = hv;
            out[((long long)(b0 + erow) * SS + step) * HH + ehid] = hv;
        }
        if (tid < 128 && step + 1 < SS)
            hx[prow * KK + HH + pxi] = xpref;
        __syncthreads();
    }
}

extern "C" void kernel_launch(void* const* d_in, const int* in_sizes, int n_in,
                              void* d_out, int out_size)
{
    const float* xg = (const float*)d_in[0];
    const float* Wm = (const float*)d_in[1];
    const float* Rm = (const float*)d_in[2];
    const float* bv = (const float*)d_in[3];
    if (n_in >= 3 && in_sizes[1] == HH * GG && in_sizes[2] == GG * II) {
        const float* t = Wm; Wm = Rm; Rm = t;
    }
    float* out = (float*)d_out;

    cudaFuncSetAttribute(slstm_kernel,
                         cudaFuncAttributeMaxDynamicSharedMemorySize, SMEM_BYTES);
    slstm_kernel<<<NCTA, NTHR, SMEM_BYTES>>>(xg, Wm, Rm, bv, out);
}